// round 12
// baseline (speedup 1.0000x reference)
#include <cuda_runtime.h>
#include <cstdint>

// Problem constants
#define BATCH 8
#define NNODE 2048
#define DIN   256
#define DOUT  128
#define ALPHA 0.2f

// Scratch (device globals: allocation-free)
__device__ float g_wh[BATCH * NNODE * DOUT];   // 8 MB
__device__ float g_s[BATCH * NNODE];
__device__ float g_d[BATCH * NNODE];

// ---------------------------------------------------------------------------
// Kernel A: wh[r][o] = sum_k x[r][k] * W[o][k],  r in [0, 16384), o in [0,128)
// CTA: 128 rows x 128 cols, 256 threads, 8x8 micro-tile, BK=16
// ---------------------------------------------------------------------------
__global__ __launch_bounds__(256) void wh_kernel(const float* __restrict__ x,
                                                 const float* __restrict__ W) {
    __shared__ float xs[16][132];   // xs[k][row]   (transposed, padded to mult of 4)
    __shared__ float ws[16][132];   // ws[k][o]

    const int tid = threadIdx.x;
    const int ty = tid >> 4;        // 0..15
    const int tx = tid & 15;        // 0..15
    const int row0 = blockIdx.x * 128;

    float acc[8][8];
#pragma unroll
    for (int m = 0; m < 8; m++)
#pragma unroll
        for (int n = 0; n < 8; n++) acc[m][n] = 0.f;

    for (int k0 = 0; k0 < DIN; k0 += 16) {
        // load x tile (128 rows x 16 k) transposed into xs
#pragma unroll
        for (int t = 0; t < 2; t++) {
            int lin4 = t * 256 + tid;          // 0..511 float4s
            int r  = lin4 >> 2;                // 0..127
            int c4 = lin4 & 3;                 // 0..3
            float4 v = *(const float4*)(x + (size_t)(row0 + r) * DIN + k0 + c4 * 4);
            xs[c4 * 4 + 0][r] = v.x;
            xs[c4 * 4 + 1][r] = v.y;
            xs[c4 * 4 + 2][r] = v.z;
            xs[c4 * 4 + 3][r] = v.w;
        }
        // load W tile (128 o x 16 k) transposed into ws
#pragma unroll
        for (int t = 0; t < 2; t++) {
            int lin4 = t * 256 + tid;
            int o  = lin4 >> 2;
            int c4 = lin4 & 3;
            float4 v = *(const float4*)(W + (size_t)o * DIN + k0 + c4 * 4);
            ws[c4 * 4 + 0][o] = v.x;
            ws[c4 * 4 + 1][o] = v.y;
            ws[c4 * 4 + 2][o] = v.z;
            ws[c4 * 4 + 3][o] = v.w;
        }
        __syncthreads();

#pragma unroll
        for (int k = 0; k < 16; k++) {
            float a[8], b[8];
            *(float4*)(a)     = *(const float4*)&xs[k][ty * 8];
            *(float4*)(a + 4) = *(const float4*)&xs[k][ty * 8 + 4];
            *(float4*)(b)     = *(const float4*)&ws[k][tx * 8];
            *(float4*)(b + 4) = *(const float4*)&ws[k][tx * 8 + 4];
#pragma unroll
            for (int m = 0; m < 8; m++)
#pragma unroll
                for (int n = 0; n < 8; n++) acc[m][n] += a[m] * b[n];
        }
        __syncthreads();
    }

#pragma unroll
    for (int m = 0; m < 8; m++) {
        int r = row0 + ty * 8 + m;
        float4 v0 = make_float4(acc[m][0], acc[m][1], acc[m][2], acc[m][3]);
        float4 v1 = make_float4(acc[m][4], acc[m][5], acc[m][6], acc[m][7]);
        *(float4*)(g_wh + (size_t)r * DOUT + tx * 8)     = v0;
        *(float4*)(g_wh + (size_t)r * DOUT + tx * 8 + 4) = v1;
    }
}

// ---------------------------------------------------------------------------
// Kernel S: s[r] = wh[r] . a_src,  d[r] = wh[r] . a_dst.  One warp per row.
// ---------------------------------------------------------------------------
__global__ __launch_bounds__(256) void sd_kernel(const float* __restrict__ a) {
    int row  = blockIdx.x * 8 + (threadIdx.x >> 5);
    int lane = threadIdx.x & 31;
    const float* whr = g_wh + (size_t)row * DOUT;
    float s = 0.f, d = 0.f;
#pragma unroll
    for (int t = 0; t < 4; t++) {
        int o = lane + t * 32;
        float v = whr[o];
        s += v * a[o];
        d += v * a[DOUT + o];
    }
#pragma unroll
    for (int off = 16; off > 0; off >>= 1) {
        s += __shfl_xor_sync(0xFFFFFFFFu, s, off);
        d += __shfl_xor_sync(0xFFFFFFFFu, d, off);
    }
    if (lane == 0) {
        g_s[row] = s;
        g_d[row] = d;
    }
}

// ---------------------------------------------------------------------------
// Kernel B: fused attention.
//   For each (b, row-tile of 128): loop over 16 column tiles of 128,
//   build w[i][j] = adj ? exp(lrelu(s_i + d_j)) : 0 in SMEM (stored transposed),
//   accumulate out[i][o] += w @ wh_tile and denom[i] += rowsum(w).
//   Epilogue: out = relu(out / denom).
// ---------------------------------------------------------------------------
#define WTS_STRIDE 132
#define SMEM_B_BYTES ((128*128 + 128*WTS_STRIDE + 128 + 128) * 4)

__global__ __launch_bounds__(256) void attn_kernel(const int* __restrict__ adj,
                                                   float* __restrict__ out) {
    extern __shared__ float sm[];
    float* whs   = sm;                           // [128][128]  wh tile (j-major)
    float* wts   = whs + 128 * 128;              // [128][132]  w transposed: wts[j][i]
    float* s_s   = wts + 128 * WTS_STRIDE;       // [128]
    float* denom = s_s + 128;                    // [128]

    const int tid = threadIdx.x;
    const int ty = tid >> 4;
    const int tx = tid & 15;
    const int b  = blockIdx.y;          // 0..7
    const int i0 = blockIdx.x * 128;    // row tile base

    if (tid < 128) {
        s_s[tid]   = g_s[b * NNODE + i0 + tid];
        denom[tid] = 0.f;
    }

    float acc[8][8];
#pragma unroll
    for (int m = 0; m < 8; m++)
#pragma unroll
        for (int n = 0; n < 8; n++) acc[m][n] = 0.f;

    __syncthreads();

    for (int jt = 0; jt < 16; jt++) {
        const int j0 = jt * 128;

        // --- load wh tile: whs[j][o] (coalesced float4) ---
#pragma unroll
        for (int t = 0; t < 16; t++) {
            int lin4 = t * 256 + tid;        // 0..4095 float4s
            int j  = lin4 >> 5;              // 32 float4 per row
            int o4 = lin4 & 31;
            *(float4*)(whs + j * 128 + o4 * 4) =
                *(const float4*)(g_wh + ((size_t)(b * NNODE + j0 + j)) * DOUT + o4 * 4);
        }

        // --- build w tile (transposed): wts[jl][il] ---
#pragma unroll 4
        for (int t = 0; t < 64; t++) {
            int lin = t * 256 + tid;
            int jl = lin & 127;
            int il = lin >> 7;
            int av = adj[((size_t)(b * NNODE + i0 + il)) * NNODE + j0 + jl];
            float e  = s_s[il] + g_d[b * NNODE + j0 + jl];
            float lr = fmaxf(e, ALPHA * e);
            float w  = (av != 0) ? __expf(lr) : 0.f;
            wts[jl * WTS_STRIDE + il] = w;
        }
        __syncthreads();

        // --- GEMM: acc[i][o] += sum_j w[i][j] * wh[j][o] ---
#pragma unroll 4
        for (int k = 0; k < 128; k++) {
            float a[8], bb[8];
            *(float4*)(a)      = *(const float4*)(wts + k * WTS_STRIDE + ty * 8);
            *(float4*)(a + 4)  = *(const float4*)(wts + k * WTS_STRIDE + ty * 8 + 4);
            *(float4*)(bb)     = *(const float4*)(whs + k * 128 + tx * 8);
            *(float4*)(bb + 4) = *(const float4*)(whs + k * 128 + tx * 8 + 4);
#pragma unroll
            for (int m = 0; m < 8; m++)
#pragma unroll
                for (int n = 0; n < 8; n++) acc[m][n] += a[m] * bb[n];
        }

        // --- denom accumulation (threads 0..127, one row each) ---
        if (tid < 128) {
            float s0 = 0.f, s1 = 0.f, s2 = 0.f, s3 = 0.f;
#pragma unroll 4
            for (int j = 0; j < 128; j += 4) {
                s0 += wts[(j + 0) * WTS_STRIDE + tid];
                s1 += wts[(j + 1) * WTS_STRIDE + tid];
                s2 += wts[(j + 2) * WTS_STRIDE + tid];
                s3 += wts[(j + 3) * WTS_STRIDE + tid];
            }
            denom[tid] += (s0 + s1) + (s2 + s3);
        }
        __syncthreads();
    }

    // --- epilogue: relu(acc / denom) ---
#pragma unroll
    for (int m = 0; m < 8; m++) {
        int i = ty * 8 + m;
        float inv = 1.f / denom[i];
        float4 v0, v1;
        v0.x = fmaxf(acc[m][0] * inv, 0.f);
        v0.y = fmaxf(acc[m][1] * inv, 0.f);
        v0.z = fmaxf(acc[m][2] * inv, 0.f);
        v0.w = fmaxf(acc[m][3] * inv, 0.f);
        v1.x = fmaxf(acc[m][4] * inv, 0.f);
        v1.y = fmaxf(acc[m][5] * inv, 0.f);
        v1.z = fmaxf(acc[m][6] * inv, 0.f);
        v1.w = fmaxf(acc[m][7] * inv, 0.f);
        size_t base = ((size_t)(b * NNODE + i0 + i)) * DOUT + tx * 8;
        *(float4*)(out + base)     = v0;
        *(float4*)(out + base + 4) = v1;
    }
}

// ---------------------------------------------------------------------------
extern "C" void kernel_launch(void* const* d_in, const int* in_sizes, int n_in,
                              void* d_out, int out_size) {
    const float* x   = (const float*)d_in[0];   // [8,2048,256]
    const int*   adj = (const int*)  d_in[1];   // [8,2048,2048]
    const float* W   = (const float*)d_in[2];   // [128,256]
    const float* a   = (const float*)d_in[3];   // [256]
    float*       out = (float*)d_out;           // [8,2048,128]

    cudaFuncSetAttribute(attn_kernel, cudaFuncAttributeMaxDynamicSharedMemorySize,
                         SMEM_B_BYTES);

    wh_kernel<<<(BATCH * NNODE) / 128, 256>>>(x, W);
    sd_kernel<<<(BATCH * NNODE) / 8, 256>>>(a);
    attn_kernel<<<dim3(NNODE / 128, BATCH), 256, SMEM_B_BYTES>>>(adj, out);
}